// round 5
// baseline (speedup 1.0000x reference)
#include <cuda_runtime.h>
#include <math_constants.h>

// ----- problem constants -----
#define B_       16
#define HID_     2048
#define NH_      16
#define NKV_     8
#define HD_      128
#define BLK_     16
#define MAXB_    256
#define QSZ_     2048   // NH*HD
#define KVSZ_    1024   // NKV*HD
#define QKVSZ_   4096
#define NSPLIT_  32
#define CHUNK_   128    // LMAX/NSPLIT
#define TB_      8      // tokens per warp per mainloop iteration
#define SCALE_   0.08838834764831845f  // 128^-0.5
#define EPS_     1e-6f

// ----- scratch -----
__device__ float g_qkvp[2][B_ * QKVSZ_];   // K-split partials of qkv proj
__device__ float g_opart[2][B_ * HID_];    // K-split partials of o proj
__device__ float g_pmax[B_ * NH_ * NSPLIT_];
__device__ float g_psum[B_ * NH_ * NSPLIT_];
__device__ float g_pacc[B_ * NH_ * NSPLIT_ * HD_];
__device__ float g_attn[B_ * QSZ_];

__device__ __forceinline__ float4 shfl_xor_f4(float4 v, int m) {
    v.x = __shfl_xor_sync(0xffffffffu, v.x, m);
    v.y = __shfl_xor_sync(0xffffffffu, v.y, m);
    v.z = __shfl_xor_sync(0xffffffffu, v.z, m);
    v.w = __shfl_xor_sync(0xffffffffu, v.w, m);
    return v;
}

// =====================================================================
// GEMV (K = 2048): y_part[ks][b, o] = x[b, Kchunk] . w[o, Kchunk]
// 256 threads = 8 warps: warps 0-3 take lower K-half of this block's
// chunk, warps 4-7 the upper half. Each warp: 4 batch rows x 8 out rows.
// grid = (out_rows/8, 2): blockIdx.y = cross-block K-split index.
// =====================================================================
__global__ void __launch_bounds__(256)
k_gemv(const float* __restrict__ x, const float* __restrict__ w,
       float* __restrict__ y, int ostride, int part_stride) {
    const int o0   = blockIdx.x * 8;
    const int lane = threadIdx.x & 31;
    const int wrp  = threadIdx.x >> 5;
    const int kh   = wrp >> 2;        // K-half within block
    const int wg   = wrp & 3;         // warp-in-group: batch rows 4*wg..
    const int b0   = wg * 4;
    const int jbase = blockIdx.y * 256 + kh * 128;  // float4 units into K

    const float4* xp = reinterpret_cast<const float4*>(x) + (size_t)b0 * 512 + jbase;
    const float4* wp = reinterpret_cast<const float4*>(w) + (size_t)o0 * 512 + jbase;

    float acc[4][8];
#pragma unroll
    for (int bb = 0; bb < 4; bb++)
#pragma unroll
        for (int r = 0; r < 8; r++) acc[bb][r] = 0.f;

#pragma unroll
    for (int it = 0; it < 4; it++) {
        const int j = lane + it * 32;
        float4 h4[4], w4[8];
#pragma unroll
        for (int bb = 0; bb < 4; bb++) h4[bb] = __ldg(xp + bb * 512 + j);
#pragma unroll
        for (int r = 0; r < 8; r++)   w4[r]  = __ldg(wp + r * 512 + j);
#pragma unroll
        for (int bb = 0; bb < 4; bb++)
#pragma unroll
            for (int r = 0; r < 8; r++) {
                acc[bb][r] += h4[bb].x * w4[r].x + h4[bb].y * w4[r].y
                            + h4[bb].z * w4[r].z + h4[bb].w * w4[r].w;
            }
    }
    // warp-reduce each acc (all lanes get the sum)
#pragma unroll
    for (int bb = 0; bb < 4; bb++)
#pragma unroll
        for (int r = 0; r < 8; r++) {
            float v = acc[bb][r];
#pragma unroll
            for (int off = 16; off; off >>= 1) v += __shfl_xor_sync(0xffffffffu, v, off);
            acc[bb][r] = v;
        }
    // lane bb*8+r deposits acc[bb][r] into smem (predicated static stores)
    __shared__ float sred[2][4][32];
#pragma unroll
    for (int bb = 0; bb < 4; bb++)
#pragma unroll
        for (int r = 0; r < 8; r++)
            if (lane == bb * 8 + r) sred[kh][wg][lane] = acc[bb][r];
    __syncthreads();
    // warps 0-3 combine the two in-block K-halves and store the partial
    if (kh == 0) {
        float v = sred[0][wg][lane] + sred[1][wg][lane];
        const int b = b0 + (lane >> 3);
        const int o = o0 + (lane & 7);
        y[(size_t)blockIdx.y * part_stride + (size_t)b * ostride + o] = v;
    }
}

// =====================================================================
// Final reduce for o-proj partials: out = p0 + p1
// =====================================================================
__global__ void __launch_bounds__(128) k_add2(float* __restrict__ out) {
    const int i = blockIdx.x * 128 + threadIdx.x;   // float4 index
    const float4 a = reinterpret_cast<const float4*>(g_opart[0])[i];
    const float4 b = reinterpret_cast<const float4*>(g_opart[1])[i];
    float4 r;  r.x = a.x + b.x;  r.y = a.y + b.y;  r.z = a.z + b.z;  r.w = a.w + b.w;
    reinterpret_cast<float4*>(out)[i] = r;
}

// =====================================================================
// Fused attention: per-block (partial-sum + RMSNorm + RoPE) prologue
// + split-KV flash decode. grid (NSPLIT, NKV, B), 128 threads.
// =====================================================================
__global__ void __launch_bounds__(128)
k_attn_split(const float* __restrict__ kc,
             const float* __restrict__ vc,
             const int*   __restrict__ btab,
             const int*   __restrict__ ctx_lens,
             const float* __restrict__ qnw,
             const float* __restrict__ knw,
             const float* __restrict__ cs_cache,
             const int*   __restrict__ positions) {
    const int s  = blockIdx.x, kv = blockIdx.y, b = blockIdx.z;
    const int tid = threadIdx.x, lane = tid & 31, wrp = tid >> 5;
    const int ctx   = ctx_lens[b];
    const int start = s * CHUNK_;
    const int end   = min(start + CHUNK_, ctx);

    __shared__ float s_head[4][HD_];   // q0, q1, k_new, v_new

    // ---- prologue ----
    {
        int off;
        const float* nw = nullptr;
        if      (wrp == 0) { off = b * QKVSZ_ + (2 * kv    ) * HD_;        nw = qnw; }
        else if (wrp == 1) { off = b * QKVSZ_ + (2 * kv + 1) * HD_;        nw = qnw; }
        else if (wrp == 2) { off = b * QKVSZ_ + QSZ_ + kv * HD_;           nw = knw; }
        else               { off = b * QKVSZ_ + QSZ_ + KVSZ_ + kv * HD_; }
        float4 x  = reinterpret_cast<const float4*>(g_qkvp[0] + off)[lane];
        float4 x1 = reinterpret_cast<const float4*>(g_qkvp[1] + off)[lane];
        x.x += x1.x;  x.y += x1.y;  x.z += x1.z;  x.w += x1.w;
        if (wrp < 3) {
            float ss = x.x * x.x + x.y * x.y + x.z * x.z + x.w * x.w;
#pragma unroll
            for (int o = 16; o; o >>= 1) ss += __shfl_xor_sync(0xffffffffu, ss, o);
            float rn = rsqrtf(ss * (1.f / HD_) + EPS_);
            const float4 nw4 = reinterpret_cast<const float4*>(nw)[lane];
            x.x *= rn * nw4.x;  x.y *= rn * nw4.y;
            x.z *= rn * nw4.z;  x.w *= rn * nw4.w;
            float4 p = shfl_xor_f4(x, 16);
            const float* cs = cs_cache + (size_t)positions[b] * HD_;
            const int d0 = (lane < 16) ? 4 * lane : 4 * lane - 64;
            const float4 c4 = *reinterpret_cast<const float4*>(cs + d0);
            const float4 s4 = *reinterpret_cast<const float4*>(cs + 64 + d0);
            if (lane < 16) {
                x.x = x.x * c4.x - p.x * s4.x;  x.y = x.y * c4.y - p.y * s4.y;
                x.z = x.z * c4.z - p.z * s4.z;  x.w = x.w * c4.w - p.w * s4.w;
            } else {
                x.x = x.x * c4.x + p.x * s4.x;  x.y = x.y * c4.y + p.y * s4.y;
                x.z = x.z * c4.z + p.z * s4.z;  x.w = x.w * c4.w + p.w * s4.w;
            }
        }
        reinterpret_cast<float4*>(s_head[wrp])[lane] = x;
    }
    __syncthreads();

    const float4 q0 = reinterpret_cast<const float4*>(s_head[0])[lane];
    const float4 q1 = reinterpret_cast<const float4*>(s_head[1])[lane];

    float m0 = -CUDART_INF_F, m1 = -CUDART_INF_F, l0 = 0.f, l1 = 0.f;
    float a0[4] = {0, 0, 0, 0}, a1[4] = {0, 0, 0, 0};
    const int* btr = btab + b * MAXB_;

    for (int base = start + wrp * TB_; base < end; base += 4 * TB_) {
        float4 k4[TB_], v4[TB_];
        float s0[TB_], s1[TB_];
#pragma unroll
        for (int i = 0; i < TB_; i++) {
            int t = base + i;
            if (t < end) {
                if (t == ctx - 1) {
                    k4[i] = reinterpret_cast<const float4*>(s_head[2])[lane];
                    v4[i] = reinterpret_cast<const float4*>(s_head[3])[lane];
                } else {
                    int slot = btr[t >> 4] * BLK_ + (t & (BLK_ - 1));
                    size_t off = ((size_t)slot * NKV_ + kv) * HD_;
                    k4[i] = __ldcs(reinterpret_cast<const float4*>(kc + off) + lane);
                    v4[i] = __ldcs(reinterpret_cast<const float4*>(vc + off) + lane);
                }
            } else {
                k4[i] = make_float4(0.f, 0.f, 0.f, 0.f);
                v4[i] = make_float4(0.f, 0.f, 0.f, 0.f);
            }
        }
#pragma unroll
        for (int i = 0; i < TB_; i++) {
            s0[i] = q0.x * k4[i].x + q0.y * k4[i].y + q0.z * k4[i].z + q0.w * k4[i].w;
            s1[i] = q1.x * k4[i].x + q1.y * k4[i].y + q1.z * k4[i].z + q1.w * k4[i].w;
        }
#pragma unroll
        for (int off = 16; off; off >>= 1) {
#pragma unroll
            for (int i = 0; i < TB_; i++) {
                s0[i] += __shfl_xor_sync(0xffffffffu, s0[i], off);
                s1[i] += __shfl_xor_sync(0xffffffffu, s1[i], off);
            }
        }
        float bm0 = -CUDART_INF_F, bm1 = -CUDART_INF_F;
#pragma unroll
        for (int i = 0; i < TB_; i++) {
            if (base + i < end) { s0[i] *= SCALE_; s1[i] *= SCALE_; }
            else                { s0[i] = -CUDART_INF_F; s1[i] = -CUDART_INF_F; }
            bm0 = fmaxf(bm0, s0[i]);
            bm1 = fmaxf(bm1, s1[i]);
        }
        float nm0 = fmaxf(m0, bm0), nm1 = fmaxf(m1, bm1);
        float f0 = __expf(m0 - nm0), f1 = __expf(m1 - nm1);
        l0 *= f0;  l1 *= f1;
#pragma unroll
        for (int j = 0; j < 4; j++) { a0[j] *= f0; a1[j] *= f1; }
#pragma unroll
        for (int i = 0; i < TB_; i++) {
            float p0 = __expf(s0[i] - nm0);
            float p1 = __expf(s1[i] - nm1);
            l0 += p0;  l1 += p1;
            a0[0] += p0 * v4[i].x;  a1[0] += p1 * v4[i].x;
            a0[1] += p0 * v4[i].y;  a1[1] += p1 * v4[i].y;
            a0[2] += p0 * v4[i].z;  a1[2] += p1 * v4[i].z;
            a0[3] += p0 * v4[i].w;  a1[3] += p1 * v4[i].w;
        }
        m0 = nm0;  m1 = nm1;
    }

    // combine the 4 warps
    __shared__ float sm[2][4], sl[2][4], sa[2][4][HD_];
    if (lane == 0) { sm[0][wrp] = m0; sm[1][wrp] = m1; sl[0][wrp] = l0; sl[1][wrp] = l1; }
#pragma unroll
    for (int j = 0; j < 4; j++) {
        sa[0][wrp][lane * 4 + j] = a0[j];
        sa[1][wrp][lane * 4 + j] = a1[j];
    }
    __syncthreads();
#pragma unroll
    for (int h = 0; h < 2; h++) {
        float M = fmaxf(fmaxf(sm[h][0], sm[h][1]), fmaxf(sm[h][2], sm[h][3]));
        float L = 0.f, A = 0.f;
#pragma unroll
        for (int wv = 0; wv < 4; wv++) {
            float mw = sm[h][wv];
            float f  = (mw == -CUDART_INF_F) ? 0.f : __expf(mw - M);
            L += sl[h][wv] * f;
            A += sa[h][wv][tid] * f;
        }
        int idx = ((b * NH_ + kv * 2 + h) * NSPLIT_ + s);
        g_pacc[(size_t)idx * HD_ + tid] = A;
        if (tid == 0) { g_pmax[idx] = M; g_psum[idx] = L; }
    }
}

// =====================================================================
// Combine splits: one warp per (b, qhead). NSPLIT_=32 -> full warp.
// =====================================================================
__global__ void __launch_bounds__(128) k_attn_combine() {
    const int bq   = blockIdx.x * 4 + (threadIdx.x >> 5);
    const int lane = threadIdx.x & 31;
    float mv = g_pmax[bq * NSPLIT_ + lane];
    float M = mv;
#pragma unroll
    for (int off = 16; off; off >>= 1) M = fmaxf(M, __shfl_xor_sync(0xffffffffu, M, off));
    float f  = (mv == -CUDART_INF_F) ? 0.f : __expf(mv - M);
    float L  = g_psum[bq * NSPLIT_ + lane] * f;
#pragma unroll
    for (int off = 16; off; off >>= 1) L += __shfl_xor_sync(0xffffffffu, L, off);
    float4 A = make_float4(0.f, 0.f, 0.f, 0.f);
#pragma unroll
    for (int s = 0; s < NSPLIT_; s++) {
        float fs = __shfl_sync(0xffffffffu, f, s);
        if (fs != 0.f) {
            float4 p = reinterpret_cast<const float4*>(
                           g_pacc + ((size_t)bq * NSPLIT_ + s) * HD_)[lane];
            A.x += fs * p.x;  A.y += fs * p.y;  A.z += fs * p.z;  A.w += fs * p.w;
        }
    }
    const float inv = 1.f / L;
    A.x *= inv;  A.y *= inv;  A.z *= inv;  A.w *= inv;
    reinterpret_cast<float4*>(g_attn + bq * HD_)[lane] = A;
}

// =====================================================================
extern "C" void kernel_launch(void* const* d_in, const int* in_sizes, int n_in,
                              void* d_out, int out_size) {
    const float* hidden   = (const float*)d_in[0];
    const int*   positions= (const int*)  d_in[1];
    const float* qkv_w    = (const float*)d_in[2];
    const float* q_norm_w = (const float*)d_in[3];
    const float* k_norm_w = (const float*)d_in[4];
    const float* o_w      = (const float*)d_in[5];
    const float* cs_cache = (const float*)d_in[6];
    const float* k_cache  = (const float*)d_in[7];
    const float* v_cache  = (const float*)d_in[8];
    // d_in[9] = slot_mapping (derived internally, unused)
    const int*   btab     = (const int*)  d_in[10];
    const int*   ctx_lens = (const int*)  d_in[11];
    float* out = (float*)d_out;

    float* d_qkvp;  cudaGetSymbolAddress((void**)&d_qkvp,  g_qkvp);
    float* d_opart; cudaGetSymbolAddress((void**)&d_opart, g_opart);
    float* d_attn;  cudaGetSymbolAddress((void**)&d_attn,  g_attn);

    k_gemv<<<dim3(QKVSZ_ / 8, 2), 256>>>(hidden, qkv_w, d_qkvp, QKVSZ_, B_ * QKVSZ_);
    k_attn_split<<<dim3(NSPLIT_, NKV_, B_), 128>>>(k_cache, v_cache, btab, ctx_lens,
                                                   q_norm_w, k_norm_w, cs_cache, positions);
    k_attn_combine<<<B_ * NH_ / 4, 128>>>();
    k_gemv<<<dim3(HID_ / 8, 2), 256>>>(d_attn, o_w, d_opart, HID_, B_ * HID_);
    k_add2<<<(B_ * HID_ / 4) / 128, 128>>>(out);
}

// round 8
// speedup vs baseline: 1.2526x; 1.2526x over previous
#include <cuda_runtime.h>
#include <math_constants.h>
#include <cstdint>

// ----- problem constants -----
#define B_       16
#define HID_     2048
#define NH_      16
#define NKV_     8
#define HD_      128
#define BLK_     16
#define MAXB_    256
#define QSZ_     2048   // NH*HD
#define KVSZ_    1024   // NKV*HD
#define QKVSZ_   4096
#define NSPLIT_  16
#define CHUNK_   256    // LMAX/NSPLIT
#define TB_      8      // tokens per warp per mainloop iteration
#define SCALE_   0.08838834764831845f  // 128^-0.5
#define EPS_     1e-6f

// GEMV pipeline config
#define GS_      4      // cp.async stages
#define NCH_     16     // K chunks (2048 / 128)

// ----- scratch -----
__device__ float g_qkv [B_ * QKVSZ_];
__device__ float g_pmax[B_ * NH_ * NSPLIT_];
__device__ float g_psum[B_ * NH_ * NSPLIT_];
__device__ float g_pacc[B_ * NH_ * NSPLIT_ * HD_];
__device__ float g_attn[B_ * QSZ_];

__device__ __forceinline__ float4 shfl_xor_f4(float4 v, int m) {
    v.x = __shfl_xor_sync(0xffffffffu, v.x, m);
    v.y = __shfl_xor_sync(0xffffffffu, v.y, m);
    v.z = __shfl_xor_sync(0xffffffffu, v.z, m);
    v.w = __shfl_xor_sync(0xffffffffu, v.w, m);
    return v;
}

#define FMA2(acc, a, b) \
    asm volatile("fma.rn.f32x2 %0, %1, %2, %0;" : "+l"(acc) : "l"(a), "l"(b))

// =====================================================================
// GEMV (K = 2048): y[b, o] = x[b,:] . w[o,:]
// 128 threads = 4 warps. Block owns 8 output rows; warp owns 4 batch
// rows x 8 out rows. Weights streamed via 4-stage cp.async pipeline
// (no registers held by loads -> deep MLP); x read from L2 with
// register prefetch. Accumulation in packed f32x2 (FFMA2, 2x fp32 rate).
// =====================================================================
__global__ void __launch_bounds__(128)
k_gemv2(const float* __restrict__ x, const float* __restrict__ w,
        float* __restrict__ y, int ostride) {
    __shared__ float4 sW[GS_][8][32];   // 16 KB
    const int tid = threadIdx.x, lane = tid & 31, wrp = tid >> 5;
    const int o0 = blockIdx.x * 8;
    const int b0 = wrp * 4;
    const float4* wp = reinterpret_cast<const float4*>(w) + (size_t)o0 * 512;
    const float4* xp = reinterpret_cast<const float4*>(x);

    // ---- async copy of one 8x32-float4 weight chunk into stage ----
    auto issue = [&](int stage, int c) {
#pragma unroll
        for (int i = 0; i < 2; i++) {
            const int idx = tid + i * 128;         // 0..255
            const int r = idx >> 5, cc = idx & 31;
            unsigned int dst = (unsigned int)__cvta_generic_to_shared(&sW[stage][r][cc]);
            const float4* src = wp + (size_t)r * 512 + c * 32 + cc;
            asm volatile("cp.async.cg.shared.global [%0], [%1], 16;"
                         :: "r"(dst), "l"(src));
        }
        asm volatile("cp.async.commit_group;");
    };

    // prologue: stages 0..GS-2
#pragma unroll
    for (int s = 0; s < GS_ - 1; s++) issue(s, s);

    // x prefetch (chunk 0) as packed u64 pairs
    unsigned long long xr[4][2];
#pragma unroll
    for (int bb = 0; bb < 4; bb++) {
        const float4* p = xp + (size_t)(b0 + bb) * 512 + lane;
        asm volatile("ld.global.nc.v2.u64 {%0,%1}, [%2];"
                     : "=l"(xr[bb][0]), "=l"(xr[bb][1]) : "l"(p));
    }

    unsigned long long acc[4][8];
#pragma unroll
    for (int bb = 0; bb < 4; bb++)
#pragma unroll
        for (int r = 0; r < 8; r++) acc[bb][r] = 0ull;

    const unsigned int wbase = (unsigned int)__cvta_generic_to_shared(&sW[0][0][lane]);

    for (int c = 0; c < NCH_; c++) {
        asm volatile("cp.async.wait_group %0;" :: "n"(GS_ - 2));
        __syncthreads();
        const int cn = c + GS_ - 1;
        if (cn < NCH_) issue(cn % GS_, cn);
        else asm volatile("cp.async.commit_group;");

        // grab current x, prefetch next chunk
        unsigned long long cur[4][2];
#pragma unroll
        for (int bb = 0; bb < 4; bb++) { cur[bb][0] = xr[bb][0]; cur[bb][1] = xr[bb][1]; }
        if (c + 1 < NCH_) {
#pragma unroll
            for (int bb = 0; bb < 4; bb++) {
                const float4* p = xp + (size_t)(b0 + bb) * 512 + (c + 1) * 32 + lane;
                asm volatile("ld.global.nc.v2.u64 {%0,%1}, [%2];"
                             : "=l"(xr[bb][0]), "=l"(xr[bb][1]) : "l"(p));
            }
        }

        const unsigned int stb = wbase + (c % GS_) * 8 * 512;  // stage base (bytes)
#pragma unroll
        for (int r = 0; r < 8; r++) {
            unsigned long long w0, w1;
            asm volatile("ld.shared.v2.u64 {%0,%1}, [%2];"
                         : "=l"(w0), "=l"(w1) : "r"(stb + r * 512));
#pragma unroll
            for (int bb = 0; bb < 4; bb++) {
                FMA2(acc[bb][r], cur[bb][0], w0);
                FMA2(acc[bb][r], cur[bb][1], w1);
            }
        }
    }

    // epilogue: unpack f32x2, warp-reduce, store
#pragma unroll
    for (int bb = 0; bb < 4; bb++)
#pragma unroll
        for (int r = 0; r < 8; r++) {
            unsigned int lo, hi;
            asm volatile("mov.b64 {%0,%1}, %2;" : "=r"(lo), "=r"(hi) : "l"(acc[bb][r]));
            float v = __uint_as_float(lo) + __uint_as_float(hi);
#pragma unroll
            for (int off = 16; off; off >>= 1) v += __shfl_xor_sync(0xffffffffu, v, off);
            if (lane == bb * 8 + r)
                y[(size_t)(b0 + bb) * ostride + o0 + r] = v;
        }
}

// =====================================================================
// Fused attention: per-block norm+RoPE prologue + split-KV flash decode.
// grid (NSPLIT, NKV, B), 128 threads (4 warps).
// =====================================================================
__global__ void __launch_bounds__(128)
k_attn_split(const float* __restrict__ kc,
             const float* __restrict__ vc,
             const int*   __restrict__ btab,
             const int*   __restrict__ ctx_lens,
             const float* __restrict__ qnw,
             const float* __restrict__ knw,
             const float* __restrict__ cs_cache,
             const int*   __restrict__ positions) {
    const int s  = blockIdx.x, kv = blockIdx.y, b = blockIdx.z;
    const int tid = threadIdx.x, lane = tid & 31, wrp = tid >> 5;
    const int ctx   = ctx_lens[b];
    const int start = s * CHUNK_;
    const int end   = min(start + CHUNK_, ctx);

    __shared__ float s_head[4][HD_];   // q0, q1, k_new, v_new

    // ---- prologue: RMSNorm + RoPE for this block's heads ----
    {
        const float* base = g_qkv + b * QKVSZ_;
        const float* src;
        const float* nw = nullptr;
        if      (wrp == 0) { src = base + (2 * kv    ) * HD_;          nw = qnw; }
        else if (wrp == 1) { src = base + (2 * kv + 1) * HD_;          nw = qnw; }
        else if (wrp == 2) { src = base + QSZ_ + kv * HD_;             nw = knw; }
        else               { src = base + QSZ_ + KVSZ_ + kv * HD_; }
        float4 x = reinterpret_cast<const float4*>(src)[lane];
        if (wrp < 3) {
            float ss = x.x * x.x + x.y * x.y + x.z * x.z + x.w * x.w;
#pragma unroll
            for (int o = 16; o; o >>= 1) ss += __shfl_xor_sync(0xffffffffu, ss, o);
            float rn = rsqrtf(ss * (1.f / HD_) + EPS_);
            const float4 nw4 = reinterpret_cast<const float4*>(nw)[lane];
            x.x *= rn * nw4.x;  x.y *= rn * nw4.y;
            x.z *= rn * nw4.z;  x.w *= rn * nw4.w;
            float4 p = shfl_xor_f4(x, 16);
            const float* cs = cs_cache + (size_t)positions[b] * HD_;
            const int d0 = (lane < 16) ? 4 * lane : 4 * lane - 64;
            const float4 c4 = *reinterpret_cast<const float4*>(cs + d0);
            const float4 s4 = *reinterpret_cast<const float4*>(cs + 64 + d0);
            if (lane < 16) {
                x.x = x.x * c4.x - p.x * s4.x;  x.y = x.y * c4.y - p.y * s4.y;
                x.z = x.z * c4.z - p.z * s4.z;  x.w = x.w * c4.w - p.w * s4.w;
            } else {
                x.x = x.x * c4.x + p.x * s4.x;  x.y = x.y * c4.y + p.y * s4.y;
                x.z = x.z * c4.z + p.z * s4.z;  x.w = x.w * c4.w + p.w * s4.w;
            }
        }
        reinterpret_cast<float4*>(s_head[wrp])[lane] = x;
    }
    __syncthreads();

    const float4 q0 = reinterpret_cast<const float4*>(s_head[0])[lane];
    const float4 q1 = reinterpret_cast<const float4*>(s_head[1])[lane];

    float m0 = -CUDART_INF_F, m1 = -CUDART_INF_F, l0 = 0.f, l1 = 0.f;
    float a0[4] = {0, 0, 0, 0}, a1[4] = {0, 0, 0, 0};
    const int* btr = btab + b * MAXB_;

    for (int base = start + wrp * TB_; base < end; base += 4 * TB_) {
        float4 k4[TB_], v4[TB_];
        float s0[TB_], s1[TB_];
#pragma unroll
        for (int i = 0; i < TB_; i++) {
            int t = base + i;
            if (t < end) {
                if (t == ctx - 1) {
                    k4[i] = reinterpret_cast<const float4*>(s_head[2])[lane];
                    v4[i] = reinterpret_cast<const float4*>(s_head[3])[lane];
                } else {
                    int slot = btr[t >> 4] * BLK_ + (t & (BLK_ - 1));
                    size_t off = ((size_t)slot * NKV_ + kv) * HD_;
                    k4[i] = __ldcs(reinterpret_cast<const float4*>(kc + off) + lane);
                    v4[i] = __ldcs(reinterpret_cast<const float4*>(vc + off) + lane);
                }
            } else {
                k4[i] = make_float4(0.f, 0.f, 0.f, 0.f);
                v4[i] = make_float4(0.f, 0.f, 0.f, 0.f);
            }
        }
#pragma unroll
        for (int i = 0; i < TB_; i++) {
            s0[i] = q0.x * k4[i].x + q0.y * k4[i].y + q0.z * k4[i].z + q0.w * k4[i].w;
            s1[i] = q1.x * k4[i].x + q1.y * k4[i].y + q1.z * k4[i].z + q1.w * k4[i].w;
        }
#pragma unroll
        for (int off = 16; off; off >>= 1) {
#pragma unroll
            for (int i = 0; i < TB_; i++) {
                s0[i] += __shfl_xor_sync(0xffffffffu, s0[i], off);
                s1[i] += __shfl_xor_sync(0xffffffffu, s1[i], off);
            }
        }
        float bm0 = -CUDART_INF_F, bm1 = -CUDART_INF_F;
#pragma unroll
        for (int i = 0; i < TB_; i++) {
            if (base + i < end) { s0[i] *= SCALE_; s1[i] *= SCALE_; }
            else                { s0[i] = -CUDART_INF_F; s1[i] = -CUDART_INF_F; }
            bm0 = fmaxf(bm0, s0[i]);
            bm1 = fmaxf(bm1, s1[i]);
        }
        float nm0 = fmaxf(m0, bm0), nm1 = fmaxf(m1, bm1);
        float f0 = __expf(m0 - nm0), f1 = __expf(m1 - nm1);
        l0 *= f0;  l1 *= f1;
#pragma unroll
        for (int j = 0; j < 4; j++) { a0[j] *= f0; a1[j] *= f1; }
#pragma unroll
        for (int i = 0; i < TB_; i++) {
            float p0 = __expf(s0[i] - nm0);
            float p1 = __expf(s1[i] - nm1);
            l0 += p0;  l1 += p1;
            a0[0] += p0 * v4[i].x;  a1[0] += p1 * v4[i].x;
            a0[1] += p0 * v4[i].y;  a1[1] += p1 * v4[i].y;
            a0[2] += p0 * v4[i].z;  a1[2] += p1 * v4[i].z;
            a0[3] += p0 * v4[i].w;  a1[3] += p1 * v4[i].w;
        }
        m0 = nm0;  m1 = nm1;
    }

    // combine the 4 warps
    __shared__ float sm[2][4], sl[2][4], sa[2][4][HD_];
    if (lane == 0) { sm[0][wrp] = m0; sm[1][wrp] = m1; sl[0][wrp] = l0; sl[1][wrp] = l1; }
#pragma unroll
    for (int j = 0; j < 4; j++) {
        sa[0][wrp][lane * 4 + j] = a0[j];
        sa[1][wrp][lane * 4 + j] = a1[j];
    }
    __syncthreads();
#pragma unroll
    for (int h = 0; h < 2; h++) {
        float M = fmaxf(fmaxf(sm[h][0], sm[h][1]), fmaxf(sm[h][2], sm[h][3]));
        float L = 0.f, A = 0.f;
#pragma unroll
        for (int wv = 0; wv < 4; wv++) {
            float mw = sm[h][wv];
            float f  = (mw == -CUDART_INF_F) ? 0.f : __expf(mw - M);
            L += sl[h][wv] * f;
            A += sa[h][wv][tid] * f;
        }
        int idx = ((b * NH_ + kv * 2 + h) * NSPLIT_ + s);
        g_pacc[(size_t)idx * HD_ + tid] = A;
        if (tid == 0) { g_pmax[idx] = M; g_psum[idx] = L; }
    }
}

// =====================================================================
// Combine splits: one warp per (b, qhead). grid 64 x 128 threads.
// =====================================================================
__global__ void __launch_bounds__(128) k_attn_combine() {
    const int bq   = blockIdx.x * 4 + (threadIdx.x >> 5);
    const int lane = threadIdx.x & 31;
    float mv = (lane < NSPLIT_) ? g_pmax[bq * NSPLIT_ + lane] : -CUDART_INF_F;
    float M = mv;
#pragma unroll
    for (int off = 16; off; off >>= 1) M = fmaxf(M, __shfl_xor_sync(0xffffffffu, M, off));
    float f  = (lane < NSPLIT_ && mv != -CUDART_INF_F) ? __expf(mv - M) : 0.f;
    float lv = (lane < NSPLIT_) ? g_psum[bq * NSPLIT_ + lane] : 0.f;
    float L = lv * f;
#pragma unroll
    for (int off = 16; off; off >>= 1) L += __shfl_xor_sync(0xffffffffu, L, off);
    float4 A = make_float4(0.f, 0.f, 0.f, 0.f);
#pragma unroll
    for (int s = 0; s < NSPLIT_; s++) {
        float fs = __shfl_sync(0xffffffffu, f, s);
        if (fs != 0.f) {
            float4 p = reinterpret_cast<const float4*>(
                           g_pacc + ((size_t)bq * NSPLIT_ + s) * HD_)[lane];
            A.x += fs * p.x;  A.y += fs * p.y;  A.z += fs * p.z;  A.w += fs * p.w;
        }
    }
    const float inv = 1.f / L;
    A.x *= inv;  A.y *= inv;  A.z *= inv;  A.w *= inv;
    reinterpret_cast<float4*>(g_attn + bq * HD_)[lane] = A;
}

// =====================================================================
extern "C" void kernel_launch(void* const* d_in, const int* in_sizes, int n_in,
                              void* d_out, int out_size) {
    const float* hidden   = (const float*)d_in[0];
    const int*   positions= (const int*)  d_in[1];
    const float* qkv_w    = (const float*)d_in[2];
    const float* q_norm_w = (const float*)d_in[3];
    const float* k_norm_w = (const float*)d_in[4];
    const float* o_w      = (const float*)d_in[5];
    const float* cs_cache = (const float*)d_in[6];
    const float* k_cache  = (const float*)d_in[7];
    const float* v_cache  = (const float*)d_in[8];
    // d_in[9] = slot_mapping (derived internally, unused)
    const int*   btab     = (const int*)  d_in[10];
    const int*   ctx_lens = (const int*)  d_in[11];
    float* out = (float*)d_out;

    float* d_qkv;  cudaGetSymbolAddress((void**)&d_qkv,  g_qkv);
    float* d_attn; cudaGetSymbolAddress((void**)&d_attn, g_attn);

    k_gemv2<<<QKVSZ_ / 8, 128>>>(hidden, qkv_w, d_qkv, QKVSZ_);
    k_attn_split<<<dim3(NSPLIT_, NKV_, B_), 128>>>(k_cache, v_cache, btab, ctx_lens,
                                                   q_norm_w, k_norm_w, cs_cache, positions);
    k_attn_combine<<<B_ * NH_ / 4, 128>>>();
    k_gemv2<<<HID_ / 8, 128>>>(d_attn, o_w, out, HID_);
}